// round 3
// baseline (speedup 1.0000x reference)
#include <cuda_runtime.h>
#include <cuda_bf16.h>
#include <math.h>

// Problem constants (fixed by setup_inputs)
#define BB 64
#define TT 1024
#define VV 512
#define SS 128
#define LL 257            // 2*S + 1 extended states
#define GSTRIDE 132       // padded row stride for gathered log-probs (16B aligned)
#define NEGF (-1e30f)

// Scratch: gathered log-probs  g[b,t,j] = logits[b,t,sym_j] - lse(b,t)
// j=0 -> blank(0), j=1..128 -> target symbols.
__device__ float g_lp[(size_t)BB * TT * GSTRIDE];   // ~34.6 MB
__device__ float g_partial[BB];

// ---------------------------------------------------------------------------
// Phase 1: per-row logsumexp over V=512 + gather of 129 symbol log-probs.
// One warp per (b,t) row.
// ---------------------------------------------------------------------------
__global__ __launch_bounds__(256) void lse_gather_kernel(
    const float* __restrict__ logits,      // [B,T,V]
    const int*   __restrict__ in_len,      // [B]
    const int*   __restrict__ tgt)         // [B,S]
{
    int gwarp = (blockIdx.x * blockDim.x + threadIdx.x) >> 5;
    int lane  = threadIdx.x & 31;
    if (gwarp >= BB * TT) return;

    int b = gwarp >> 10;          // / TT
    int t = gwarp & (TT - 1);
    if (t >= in_len[b]) return;   // frames past utterance length are never read

    const float4* row4 = (const float4*)(logits + (size_t)gwarp * VV);

    // load 16 floats per lane (coalesced float4), running max
    float4 v[4];
    float mx = -INFINITY;
#pragma unroll
    for (int i = 0; i < 4; i++) {
        v[i] = row4[lane + 32 * i];
        mx = fmaxf(mx, fmaxf(fmaxf(v[i].x, v[i].y), fmaxf(v[i].z, v[i].w)));
    }
#pragma unroll
    for (int o = 16; o > 0; o >>= 1)
        mx = fmaxf(mx, __shfl_xor_sync(0xFFFFFFFFu, mx, o));

    float sum = 0.f;
#pragma unroll
    for (int i = 0; i < 4; i++) {
        sum += __expf(v[i].x - mx) + __expf(v[i].y - mx) +
               __expf(v[i].z - mx) + __expf(v[i].w - mx);
    }
#pragma unroll
    for (int o = 16; o > 0; o >>= 1)
        sum += __shfl_xor_sync(0xFFFFFFFFu, sum, o);

    float lse = mx + __logf(sum);

    // gather log-probs at blank + 128 target symbols (row is hot in L1)
    const float* rowf = logits + (size_t)gwarp * VV;
    const int*   tb   = tgt + b * SS;
    float*       out  = g_lp + (size_t)gwarp * GSTRIDE;
#pragma unroll
    for (int j = lane; j < SS + 1; j += 32) {
        int sym = (j == 0) ? 0 : tb[j - 1];
        out[j] = rowf[sym] - lse;
    }
}

// ---------------------------------------------------------------------------
// Phase 2: CTC alpha recursion. One CTA per batch element, one thread per
// extended state. Double-buffered shared alpha -> one barrier per time step.
// ---------------------------------------------------------------------------
__global__ __launch_bounds__(288) void ctc_alpha_kernel(
    const int* __restrict__ in_len,
    const int* __restrict__ tgt,
    const int* __restrict__ tgt_len)
{
    const int b = blockIdx.x;
    const int s = threadIdx.x;
    const bool active = (s < LL);

    // sh[.][0..1] are the s=-2,-1 guards; real state s lives at index s+2
    __shared__ float sh[2][LL + 2];
    if (s < 2) { sh[0][s] = NEGF; sh[1][s] = NEGF; }

    // column in gathered row: even state -> blank (j=0), odd state s -> j=(s+1)/2
    const int col = (s & 1) ? ((s + 1) >> 1) : 0;

    // skip transition allowed iff odd state, s>=3, and label != label-1
    bool skip = false;
    if (active && (s & 1) && s >= 3) {
        int k = (s - 1) >> 1;
        skip = (tgt[b * SS + k] != tgt[b * SS + k - 1]);
    }

    const float* grow = g_lp + (size_t)b * TT * GSTRIDE;
    const int len = in_len[b];

    // t = 0 init
    float a = NEGF;
    if (active && s < 2) a = grow[col];

    // prefetch lp for t = 1 (len >= 512 > 1 always for this problem)
    float lp = active ? grow[GSTRIDE + col] : 0.f;

    int p = 0;
    for (int t = 1; t < len; t++) {
        // prefetch next step's lp before the barrier (hides global latency)
        float lp_next = 0.f;
        if (active && (t + 1) < len)
            lp_next = grow[(size_t)(t + 1) * GSTRIDE + col];

        if (active) sh[p][s + 2] = a;
        __syncthreads();

        if (active) {
            float a1 = sh[p][s + 1];
            float a2 = skip ? sh[p][s] : NEGF;
            float m  = fmaxf(a, fmaxf(a1, a2));
            float sm = __expf(a - m) + __expf(a1 - m) + __expf(a2 - m);
            a = m + __logf(sm) + lp;
        }
        lp = lp_next;
        p ^= 1;
    }

    if (active) sh[p][s + 2] = a;
    __syncthreads();

    if (s == 0) {
        int e = 2 * tgt_len[b];
        float x = sh[p][e + 2];       // alpha[2*tl]
        float y = sh[p][e + 1];       // alpha[2*tl - 1]
        float m = fmaxf(x, y);
        float ll = m + __logf(__expf(x - m) + __expf(y - m));
        float loss = -ll;
        if (loss > 1e29f) loss = 0.f;     // zero_infinity
        g_partial[b] = loss;
    }
}

// ---------------------------------------------------------------------------
// Phase 3: deterministic reduction of 64 per-batch losses -> scalar
// ---------------------------------------------------------------------------
__global__ void reduce_loss_kernel(float* __restrict__ out)
{
    int l = threadIdx.x;                   // 32 threads
    float v = g_partial[l] + g_partial[l + 32];
#pragma unroll
    for (int o = 16; o > 0; o >>= 1)
        v += __shfl_xor_sync(0xFFFFFFFFu, v, o);
    if (l == 0) out[0] = v;
}

// ---------------------------------------------------------------------------
extern "C" void kernel_launch(void* const* d_in, const int* in_sizes, int n_in,
                              void* d_out, int out_size)
{
    const float* logits  = (const float*)d_in[0];   // [B,T,V] fp32
    const int*   in_len  = (const int*)d_in[1];     // [B]
    const int*   tgt     = (const int*)d_in[2];     // [B,S]
    const int*   tgt_len = (const int*)d_in[3];     // [B]
    float*       out     = (float*)d_out;

    // Phase 1: one warp per row; 65536 warps -> 8192 blocks of 256 threads
    lse_gather_kernel<<<(BB * TT) / 8, 256>>>(logits, in_len, tgt);

    // Phase 2: one CTA per batch element
    ctc_alpha_kernel<<<BB, 288>>>(in_len, tgt, tgt_len);

    // Phase 3: scalar reduce
    reduce_loss_kernel<<<1, 32>>>(out);
}

// round 7
// speedup vs baseline: 1.7425x; 1.7425x over previous
#include <cuda_runtime.h>
#include <cuda_bf16.h>
#include <cstdint>
#include <math.h>

// Problem constants (fixed by setup_inputs)
#define BB 64
#define TT 1024
#define VV 512
#define SS 128
#define LL 257            // 2*S + 1 extended states
#define GSTRIDE 132       // padded row stride for gathered log-probs
#define NEGF (-1e30f)
#define PF   6            // cp.async prefetch depth (rows ahead)
#define RING 8            // ring slots (power of 2, > PF+1)

// Scratch: gathered log-probs  g[b,t,j] = logits[b,t,sym_j] - lse(b,t)
// j=0 -> blank(0), j=1..128 -> target symbols.
__device__ float g_lp[(size_t)BB * TT * GSTRIDE];   // ~34.6 MB
__device__ float g_partial[BB];

// ---------------------------------------------------------------------------
// Phase 1: per-row logsumexp over V=512 + gather of 129 symbol log-probs.
// One warp per (b,t) row.  (Measured 21.9us @ 61.7% DRAM — near stream bound.)
// ---------------------------------------------------------------------------
__global__ __launch_bounds__(256) void lse_gather_kernel(
    const float* __restrict__ logits,      // [B,T,V]
    const int*   __restrict__ in_len,      // [B]
    const int*   __restrict__ tgt)         // [B,S]
{
    int gwarp = (blockIdx.x * blockDim.x + threadIdx.x) >> 5;
    int lane  = threadIdx.x & 31;
    if (gwarp >= BB * TT) return;

    int b = gwarp >> 10;          // / TT
    int t = gwarp & (TT - 1);
    if (t >= in_len[b]) return;   // frames past utterance length are never read

    const float4* row4 = (const float4*)(logits + (size_t)gwarp * VV);

    float4 v[4];
    float mx = -INFINITY;
#pragma unroll
    for (int i = 0; i < 4; i++) {
        v[i] = row4[lane + 32 * i];
        mx = fmaxf(mx, fmaxf(fmaxf(v[i].x, v[i].y), fmaxf(v[i].z, v[i].w)));
    }
#pragma unroll
    for (int o = 16; o > 0; o >>= 1)
        mx = fmaxf(mx, __shfl_xor_sync(0xFFFFFFFFu, mx, o));

    float sum = 0.f;
#pragma unroll
    for (int i = 0; i < 4; i++) {
        sum += __expf(v[i].x - mx) + __expf(v[i].y - mx) +
               __expf(v[i].z - mx) + __expf(v[i].w - mx);
    }
#pragma unroll
    for (int o = 16; o > 0; o >>= 1)
        sum += __shfl_xor_sync(0xFFFFFFFFu, sum, o);

    float lse = mx + __logf(sum);

    const float* rowf = logits + (size_t)gwarp * VV;
    const int*   tb   = tgt + b * SS;
    float*       out  = g_lp + (size_t)gwarp * GSTRIDE;
#pragma unroll
    for (int j = lane; j < SS + 1; j += 32) {
        int sym = (j == 0) ? 0 : tb[j - 1];
        out[j] = rowf[sym] - lse;
    }
}

// ---------------------------------------------------------------------------
// Phase 2: CTC alpha recursion. One CTA per batch element, one thread per
// extended state. lp rows staged PF steps ahead via cp.async ring buffer, so
// the only post-barrier latency is shared-memory.
// ---------------------------------------------------------------------------
__device__ __forceinline__ void cp_async_f32(unsigned int dst_smem, const float* src)
{
    asm volatile("cp.async.ca.shared.global [%0], [%1], 4;\n"
                 :: "r"(dst_smem), "l"(src));
}
__device__ __forceinline__ void cp_commit()
{
    asm volatile("cp.async.commit_group;\n");
}
__device__ __forceinline__ void cp_wait_pf()
{
    asm volatile("cp.async.wait_group %0;\n" :: "n"(PF));
}

__global__ __launch_bounds__(288) void ctc_alpha_kernel(
    const int* __restrict__ in_len,
    const int* __restrict__ tgt,
    const int* __restrict__ tgt_len)
{
    const int b = blockIdx.x;
    const int s = threadIdx.x;
    const bool active = (s < LL);
    const bool loader = (s < SS + 1);   // threads 0..128 stage lp rows

    // sh[.][0..1] are the s=-2,-1 guards; real state s lives at index s+2
    __shared__ float sh[2][LL + 2];
    __shared__ float shlp[RING][GSTRIDE];
    if (s < 2) { sh[0][s] = NEGF; sh[1][s] = NEGF; }

    // column in gathered row: even state -> blank (j=0), odd state s -> (s+1)/2
    const int col = (s & 1) ? ((s + 1) >> 1) : 0;

    bool skip = false;
    if (active && (s & 1) && s >= 3) {
        int k = (s - 1) >> 1;
        skip = (tgt[b * SS + k] != tgt[b * SS + k - 1]);
    }

    const float* grow = g_lp + (size_t)b * TT * GSTRIDE;
    const int len = in_len[b];           // len >= 512 for this problem

    unsigned int my_slot_base = 0;
    if (loader)
        my_slot_base = (unsigned int)__cvta_generic_to_shared(&shlp[0][s]);

    // Prologue: stage rows 1..PF (group g <-> row g)
#pragma unroll
    for (int r = 1; r <= PF; r++) {
        if (loader)
            cp_async_f32(my_slot_base + (unsigned int)(r & (RING - 1)) * (GSTRIDE * 4),
                         grow + (size_t)r * GSTRIDE + s);
        cp_commit();
    }

    // t = 0 init
    float a = NEGF;
    if (s < 2) a = grow[col];

    int p = 0;
    for (int t = 1; t < len; t++) {
        // stage row t+PF (slot overwritten is 2 barriers past its last read)
        int r = t + PF;
        if (loader && r < len)
            cp_async_f32(my_slot_base + (unsigned int)(r & (RING - 1)) * (GSTRIDE * 4),
                         grow + (size_t)r * GSTRIDE + s);
        cp_commit();                      // exactly one group per iteration

        if (active) sh[p][s + 2] = a;
        cp_wait_pf();                     // row t complete in issuing threads
        __syncthreads();                  // ...and visible to all threads

        if (active) {
            float lp = shlp[t & (RING - 1)][col];
            float a1 = sh[p][s + 1];
            float a2 = skip ? sh[p][s] : NEGF;
            float m  = fmaxf(a, fmaxf(a1, a2));
            float sm = __expf(a - m) + __expf(a1 - m) + __expf(a2 - m);
            a = m + __logf(sm) + lp;
        }
        p ^= 1;
    }

    if (active) sh[p][s + 2] = a;
    __syncthreads();

    if (s == 0) {
        int e = 2 * tgt_len[b];
        float x = sh[p][e + 2];       // alpha[2*tl]
        float y = sh[p][e + 1];       // alpha[2*tl - 1]
        float m = fmaxf(x, y);
        float ll = m + __logf(__expf(x - m) + __expf(y - m));
        float loss = -ll;
        if (loss > 1e29f) loss = 0.f;     // zero_infinity
        g_partial[b] = loss;
    }
}

// ---------------------------------------------------------------------------
// Phase 3: deterministic reduction of 64 per-batch losses -> scalar
// ---------------------------------------------------------------------------
__global__ void reduce_loss_kernel(float* __restrict__ out)
{
    int l = threadIdx.x;                   // 32 threads
    float v = g_partial[l] + g_partial[l + 32];
#pragma unroll
    for (int o = 16; o > 0; o >>= 1)
        v += __shfl_xor_sync(0xFFFFFFFFu, v, o);
    if (l == 0) out[0] = v;
}

// ---------------------------------------------------------------------------
extern "C" void kernel_launch(void* const* d_in, const int* in_sizes, int n_in,
                              void* d_out, int out_size)
{
    const float* logits  = (const float*)d_in[0];   // [B,T,V] fp32
    const int*   in_len  = (const int*)d_in[1];     // [B]
    const int*   tgt     = (const int*)d_in[2];     // [B,S]
    const int*   tgt_len = (const int*)d_in[3];     // [B]
    float*       out     = (float*)d_out;

    lse_gather_kernel<<<(BB * TT) / 8, 256>>>(logits, in_len, tgt);
    ctc_alpha_kernel<<<BB, 288>>>(in_len, tgt, tgt_len);
    reduce_loss_kernel<<<1, 32>>>(out);
}